// round 7
// baseline (speedup 1.0000x reference)
#include <cuda_runtime.h>

#define D       8
#define MP      64
#define CELLS_CAP (1 << 20)
#define SCAN_T  1024
#define NBLK    (CELLS_CAP / SCAN_T)
#define N_CAP   (1 << 21)

__device__ int g_cell_count[CELLS_CAP];
__device__ int g_cell_cursor[CELLS_CAP];
__device__ int g_cell_start[CELLS_CAP];
__device__ int g_cell_vid[CELLS_CAP];
__device__ int g_bsum_cnt[NBLK];
__device__ int g_bsum_occ[NBLK];
__device__ int g_lin[N_CAP];
__device__ int g_slot[N_CAP];

// XLA-GPU-style full-range (non-IEEE) f32 divide.
__device__ __forceinline__ float div_full(float a, float b) {
    float r;
    asm("div.full.f32 %0, %1, %2;" : "=f"(r) : "f"(a), "f"(b));
    return r;
}

__global__ void k_zero(float* __restrict__ out, int out_n4) {
    int i = blockIdx.x * blockDim.x + threadIdx.x;
    int stride = gridDim.x * blockDim.x;
    int4 z4 = make_int4(0, 0, 0, 0);
    for (int j = i; j < CELLS_CAP / 4; j += stride) {
        ((int4*)g_cell_count)[j] = z4;
        ((int4*)g_cell_cursor)[j] = z4;
    }
    float4 f4 = make_float4(0.f, 0.f, 0.f, 0.f);
    for (int j = i; j < out_n4; j += stride) {
        ((float4*)out)[j] = f4;
    }
}

__device__ __forceinline__ int block_excl_scan(int val, int* sh, int& total) {
    unsigned lane = threadIdx.x & 31u;
    unsigned wid  = threadIdx.x >> 5;
    int v = val;
#pragma unroll
    for (int o = 1; o < 32; o <<= 1) {
        int n = __shfl_up_sync(0xffffffffu, v, o);
        if (lane >= (unsigned)o) v += n;
    }
    if (lane == 31) sh[wid] = v;
    __syncthreads();
    if (wid == 0) {
        int nw = blockDim.x >> 5;
        int w = (lane < (unsigned)nw) ? sh[lane] : 0;
#pragma unroll
        for (int o = 1; o < 32; o <<= 1) {
            int n = __shfl_up_sync(0xffffffffu, w, o);
            if (lane >= (unsigned)o) w += n;
        }
        sh[lane] = w;
    }
    __syncthreads();
    int warpOff = wid ? sh[wid - 1] : 0;
    total = sh[(blockDim.x >> 5) - 1];
    __syncthreads();
    return warpOff + (v - val);
}

__global__ void k_bin(const float* __restrict__ pts,
                      const float* __restrict__ vs,
                      const float* __restrict__ rmin,
                      const float* __restrict__ rmax, int N) {
    int i = blockIdx.x * blockDim.x + threadIdx.x;
    if (i >= N) return;
    float v0 = vs[0], v1 = vs[1], v2 = vs[2];
    float m0 = rmin[0], m1 = rmin[1], m2 = rmin[2];
    int Gx = (int)rintf(div_full(rmax[0] - m0, v0));
    int Gy = (int)rintf(div_full(rmax[1] - m1, v1));
    int Gz = (int)rintf(div_full(rmax[2] - m2, v2));
    float x = pts[(size_t)i * D + 0];
    float y = pts[(size_t)i * D + 1];
    float z = pts[(size_t)i * D + 2];
    int ix = (int)floorf(div_full(x - m0, v0));
    int iy = (int)floorf(div_full(y - m1, v1));
    int iz = (int)floorf(div_full(z - m2, v2));
    int lin = -1;
    if (ix >= 0 && ix < Gx && iy >= 0 && iy < Gy && iz >= 0 && iz < Gz) {
        lin = (iz * Gy + iy) * Gx + ix;
        if (lin >= CELLS_CAP) lin = -1;
    }
    g_lin[i] = lin;
    if (lin >= 0) atomicAdd(&g_cell_count[lin], 1);
}

__global__ void k_scan1() {
    __shared__ int sh[32];
    int idx = blockIdx.x * SCAN_T + threadIdx.x;
    int c   = g_cell_count[idx];
    int occ = (c > 0) ? 1 : 0;
    int tot1, tot2;
    block_excl_scan(c,   sh, tot1);
    block_excl_scan(occ, sh, tot2);
    if (threadIdx.x == 0) {
        g_bsum_cnt[blockIdx.x] = tot1;
        g_bsum_occ[blockIdx.x] = tot2;
    }
}

__global__ void k_scan2() {
    __shared__ int sh[32];
    int t = threadIdx.x;
    int c = g_bsum_cnt[t];
    int o = g_bsum_occ[t];
    int tot;
    int ec = block_excl_scan(c, sh, tot);
    int eo = block_excl_scan(o, sh, tot);
    g_bsum_cnt[t] = ec;
    g_bsum_occ[t] = eo;
}

__global__ void k_scan3() {
    __shared__ int sh[32];
    int idx = blockIdx.x * SCAN_T + threadIdx.x;
    int c   = g_cell_count[idx];
    int occ = (c > 0) ? 1 : 0;
    int tot;
    int ec = block_excl_scan(c,   sh, tot) + g_bsum_cnt[blockIdx.x];
    int eo = block_excl_scan(occ, sh, tot) + g_bsum_occ[blockIdx.x];
    g_cell_start[idx] = ec;
    g_cell_vid[idx]   = eo;
}

__global__ void k_scatter(int N) {
    int i = blockIdx.x * blockDim.x + threadIdx.x;
    if (i >= N) return;
    int lin = g_lin[i];
    if (lin < 0) return;
    int pos = g_cell_start[lin] + atomicAdd(&g_cell_cursor[lin], 1);
    g_slot[pos] = i;
}

__global__ void k_final(const float* __restrict__ pts,
                        const float* __restrict__ vs,
                        const float* __restrict__ rmin,
                        const float* __restrict__ rmax,
                        float* __restrict__ out, int MV) {
    int c = blockIdx.x * blockDim.x + threadIdx.x;
    if (c >= CELLS_CAP) return;
    int cnt = g_cell_count[c];
    if (cnt == 0) return;
    int vid = g_cell_vid[c];
    if (vid >= MV) return;
    int start = g_cell_start[c];

    int buf[MP];
    int k = 0;
    for (int j = 0; j < cnt; ++j) {
        int p = g_slot[start + j];
        if (k < MP) {
            int pos = k++;
            while (pos > 0 && buf[pos - 1] > p) { buf[pos] = buf[pos - 1]; --pos; }
            buf[pos] = p;
        } else if (p < buf[MP - 1]) {
            int pos = MP - 1;
            while (pos > 0 && buf[pos - 1] > p) { buf[pos] = buf[pos - 1]; --pos; }
            buf[pos] = p;
        }
    }

    int Gx = (int)rintf(div_full(rmax[0] - rmin[0], vs[0]));
    int Gy = (int)rintf(div_full(rmax[1] - rmin[1], vs[1]));
    int x = c % Gx;
    int y = (c / Gx) % Gy;
    int z = c / (Gx * Gy);

    float* ov = out + (size_t)vid * MP * D;
    for (int r = 0; r < k; ++r) {
        int p = buf[r];
        const float4* src = (const float4*)(pts + (size_t)p * D);
        float4 a = src[0];
        float4 b = src[1];
        float4* dst = (float4*)(ov + r * D);
        dst[0] = a;
        dst[1] = b;
    }
    size_t cb = (size_t)MV * MP * D;
    out[cb + (size_t)vid * 3 + 0] = (float)z;
    out[cb + (size_t)vid * 3 + 1] = (float)y;
    out[cb + (size_t)vid * 3 + 2] = (float)x;
    out[cb + (size_t)MV * 3 + vid] = (float)k;
}

extern "C" void kernel_launch(void* const* d_in, const int* in_sizes, int n_in,
                              void* d_out, int out_size) {
    const float* pts  = (const float*)d_in[0];
    const float* vs   = (const float*)d_in[1];
    const float* rmin = (const float*)d_in[2];
    const float* rmax = (const float*)d_in[3];

    int N  = in_sizes[0] / D;
    int MV = out_size / (MP * D + 3 + 1);

    int tb = 256;
    k_zero<<<2048, tb>>>((float*)d_out, out_size / 4);
    k_bin<<<(N + tb - 1) / tb, tb>>>(pts, vs, rmin, rmax, N);
    k_scan1<<<NBLK, SCAN_T>>>();
    k_scan2<<<1, SCAN_T>>>();
    k_scan3<<<NBLK, SCAN_T>>>();
    k_scatter<<<(N + tb - 1) / tb, tb>>>(N);
    k_final<<<CELLS_CAP / tb, tb>>>(pts, vs, rmin, rmax, (float*)d_out, MV);
}